// round 2
// baseline (speedup 1.0000x reference)
#include <cuda_runtime.h>

// ---------------------------------------------------------------------------
// GCN 2-layer forward on GB300.
//   h  = x @ W1                                   (50000x512 @ 512x256)
//   a1 = Dinv (A+I) Dinv h ;  a1 += b1 ; ELU ; dropout(p=0.25, jax threefry)
//   p  = a1 @ W2                                  (50000x256 @ 256x1)
//   out= Dinv (A+I) Dinv p + b2
//
// All scratch lives in __device__ globals, referenced ONLY from device code
// (passing a __device__ symbol as a host-side kernel argument is UB and was
// the Round-1 failure).
// ---------------------------------------------------------------------------

#define NMAX 50048
#define CIN  512
#define CH   256

__device__ float g_DEG [NMAX];
__device__ float g_DINV[NMAX];
__device__ float g_H   [(size_t)NMAX * CH];
__device__ float g_AGG [(size_t)NMAX * CH];
__device__ float g_P   [NMAX];
__device__ int   g_is64;

// ---------------------------------------------------------------------------
// edge_index dtype detection (int64 vs int32). For int64 little-endian data
// with values < 50000, every odd 32-bit word (high half) is zero.
// ---------------------------------------------------------------------------
__global__ void detect_kernel(const unsigned* __restrict__ words, int E) {
    if (threadIdx.x == 0 && blockIdx.x == 0) {
        int n = E < 256 ? E : 256;
        unsigned acc = 0u;
        for (int i = 0; i < n; i++) acc |= words[2 * i + 1];
        g_is64 = (acc == 0u) ? 1 : 0;
    }
}

__device__ __forceinline__ int edge_at(const void* ei, int is64, long long idx) {
    if (is64) return (int)((const long long*)ei)[idx];
    return ((const int*)ei)[idx];
}

// ---------------------------------------------------------------------------
// Degree / normalization
// ---------------------------------------------------------------------------
__global__ void deg_init_kernel(int M) {
    int v = blockIdx.x * blockDim.x + threadIdx.x;
    if (v < M) g_DEG[v] = 1.0f;   // self loop
}

__global__ void deg_acc_kernel(const void* __restrict__ ei, int E) {
    int e = blockIdx.x * blockDim.x + threadIdx.x;
    if (e >= E) return;
    int is64 = g_is64;
    int d = edge_at(ei, is64, (long long)E + e);   // dst = edge_index[1][e]
    atomicAdd(&g_DEG[d], 1.0f);
}

__global__ void dinv_kernel(int M) {
    int v = blockIdx.x * blockDim.x + threadIdx.x;
    if (v < M) g_DINV[v] = rsqrtf(g_DEG[v]);
}

// ---------------------------------------------------------------------------
// GEMM1: g_H[M,256] = X[M,512] @ W1[512,256]. 128x128x8 tile, 8x8 per thread.
// Writes the __device__ global directly (no symbol-as-argument).
// ---------------------------------------------------------------------------
__global__ __launch_bounds__(256) void gemm1_kernel(
    const float* __restrict__ A,   // [M,512]
    const float* __restrict__ B,   // [512,256]
    int M)
{
    const int K = CIN, N = CH;
    __shared__ float As[8][128];
    __shared__ float Bs[8][128];

    int tid  = threadIdx.x;
    int row0 = blockIdx.x * 128;
    int col0 = blockIdx.y * 128;

    int ty = tid / 16, tx = tid % 16;          // 16x16 threads, 8x8 each
    float acc[8][8];
    #pragma unroll
    for (int i = 0; i < 8; i++)
        #pragma unroll
        for (int j = 0; j < 8; j++) acc[i][j] = 0.0f;

    int a_row = tid >> 1;                      // 0..127
    int a_k   = (tid & 1) * 4;                 // 0 or 4
    int b_k   = tid >> 5;                      // 0..7
    int b_col = (tid & 31) * 4;                // 0..124

    for (int k0 = 0; k0 < K; k0 += 8) {
        float4 av = make_float4(0.f, 0.f, 0.f, 0.f);
        int gr = row0 + a_row;
        if (gr < M) av = *(const float4*)(A + (size_t)gr * K + k0 + a_k);
        As[a_k + 0][a_row] = av.x;
        As[a_k + 1][a_row] = av.y;
        As[a_k + 2][a_row] = av.z;
        As[a_k + 3][a_row] = av.w;

        float4 bv = *(const float4*)(B + (size_t)(k0 + b_k) * N + col0 + b_col);
        *(float4*)&Bs[b_k][b_col] = bv;
        __syncthreads();

        #pragma unroll
        for (int kk = 0; kk < 8; kk++) {
            float ar[8], br[8];
            #pragma unroll
            for (int i = 0; i < 8; i++) ar[i] = As[kk][ty * 8 + i];
            #pragma unroll
            for (int j = 0; j < 8; j++) br[j] = Bs[kk][tx * 8 + j];
            #pragma unroll
            for (int i = 0; i < 8; i++)
                #pragma unroll
                for (int j = 0; j < 8; j++)
                    acc[i][j] += ar[i] * br[j];
        }
        __syncthreads();
    }

    #pragma unroll
    for (int i = 0; i < 8; i++) {
        int gr = row0 + ty * 8 + i;
        if (gr < M) {
            #pragma unroll
            for (int j = 0; j < 8; j += 4) {
                *(float4*)(g_H + (size_t)gr * N + col0 + tx * 8 + j) =
                    make_float4(acc[i][j], acc[i][j+1], acc[i][j+2], acc[i][j+3]);
            }
        }
    }
}

// ---------------------------------------------------------------------------
// Aggregation layer 1: AGG = selfloop + edge scatter (atomics)
// ---------------------------------------------------------------------------
__global__ void selfloop1_kernel(int n) {
    int i = blockIdx.x * blockDim.x + threadIdx.x;
    if (i >= n) return;
    int v = i >> 8;
    float di = g_DINV[v];
    g_AGG[i] = di * di * g_H[i];
}

__global__ void scatter1_kernel(const void* __restrict__ ei, int E) {
    long long t = (long long)blockIdx.x * blockDim.x + threadIdx.x;
    int e = (int)(t >> 6);
    int q = (int)(t & 63);
    if (e >= E) return;
    int is64 = g_is64;
    int s = edge_at(ei, is64, e);
    int d = edge_at(ei, is64, (long long)E + e);
    float norm = g_DINV[s] * g_DINV[d];
    float4 hv = *(const float4*)(g_H + (size_t)s * CH + q * 4);
    float* out = g_AGG + (size_t)d * CH + q * 4;
    atomicAdd(out + 0, norm * hv.x);
    atomicAdd(out + 1, norm * hv.y);
    atomicAdd(out + 2, norm * hv.z);
    atomicAdd(out + 3, norm * hv.w);
}

// ---------------------------------------------------------------------------
// Epilogue: bias + ELU + dropout (JAX threefry2x32, partitionable mode).
// bits(i) = o0 ^ o1 of threefry(key=(0,42), counts=(0, i)); u=(bits>>9)|1.0 - 1
// keep = u < 0.75 ; kept values scaled by 1/0.75. Writes H in place.
// ---------------------------------------------------------------------------
__device__ __forceinline__ void threefry2x32(unsigned c0, unsigned c1,
                                             unsigned& o0, unsigned& o1) {
    const unsigned ks0 = 0u, ks1 = 42u;
    const unsigned ks2 = 0x1BD11BDAu ^ ks0 ^ ks1;
    unsigned x0 = c0 + ks0;
    unsigned x1 = c1 + ks1;
#define TF_ROUND(r) { x0 += x1; x1 = (x1 << (r)) | (x1 >> (32 - (r))); x1 ^= x0; }
    TF_ROUND(13) TF_ROUND(15) TF_ROUND(26) TF_ROUND(6)
    x0 += ks1; x1 += ks2 + 1u;
    TF_ROUND(17) TF_ROUND(29) TF_ROUND(16) TF_ROUND(24)
    x0 += ks2; x1 += ks0 + 2u;
    TF_ROUND(13) TF_ROUND(15) TF_ROUND(26) TF_ROUND(6)
    x0 += ks0; x1 += ks1 + 3u;
    TF_ROUND(17) TF_ROUND(29) TF_ROUND(16) TF_ROUND(24)
    x0 += ks1; x1 += ks2 + 4u;
    TF_ROUND(13) TF_ROUND(15) TF_ROUND(26) TF_ROUND(6)
    x0 += ks2; x1 += ks0 + 5u;
#undef TF_ROUND
    o0 = x0; o1 = x1;
}

__global__ void epilogue_kernel(const float* __restrict__ b1, int n) {
    int i = blockIdx.x * blockDim.x + threadIdx.x;
    if (i >= n) return;
    unsigned o0, o1;
    threefry2x32(0u, (unsigned)i, o0, o1);
    unsigned bits = o0 ^ o1;
    float u = __uint_as_float((bits >> 9) | 0x3F800000u) - 1.0f;
    float v = g_AGG[i] + b1[i & (CH - 1)];
    v = v > 0.0f ? v : expm1f(v);
    g_H[i] = (u < 0.75f) ? v * (1.0f / 0.75f) : 0.0f;
}

// ---------------------------------------------------------------------------
// GEMM2: P[v] = dot(H[v,:], W2[:,0]).  One warp per node.
// ---------------------------------------------------------------------------
__global__ void gemm2_kernel(const float* __restrict__ W2, int M) {
    int gt   = blockIdx.x * blockDim.x + threadIdx.x;
    int warp = gt >> 5;
    int lane = gt & 31;
    if (warp >= M) return;
    const float4* row = (const float4*)(g_H + (size_t)warp * CH);
    const float4* w   = (const float4*)W2;
    float s = 0.0f;
    #pragma unroll
    for (int j = lane; j < CH / 4; j += 32) {
        float4 a = row[j];
        float4 b = w[j];
        s += a.x * b.x + a.y * b.y + a.z * b.z + a.w * b.w;
    }
    #pragma unroll
    for (int o = 16; o > 0; o >>= 1) s += __shfl_xor_sync(0xffffffffu, s, o);
    if (lane == 0) g_P[warp] = s;
}

// ---------------------------------------------------------------------------
// Aggregation layer 2 (scalar): out[v] = dinv^2 * P[v] + b2 + edge terms
// ---------------------------------------------------------------------------
__global__ void out_init_kernel(float* __restrict__ out,
                                const float* __restrict__ b2, int M) {
    int v = blockIdx.x * blockDim.x + threadIdx.x;
    if (v >= M) return;
    float di = g_DINV[v];
    out[v] = di * di * g_P[v] + b2[0];
}

__global__ void scatter2_kernel(const void* __restrict__ ei,
                                float* __restrict__ out, int E) {
    int e = blockIdx.x * blockDim.x + threadIdx.x;
    if (e >= E) return;
    int is64 = g_is64;
    int s = edge_at(ei, is64, e);
    int d = edge_at(ei, is64, (long long)E + e);
    atomicAdd(&out[d], g_DINV[s] * g_DINV[d] * g_P[s]);
}

// ---------------------------------------------------------------------------
extern "C" void kernel_launch(void* const* d_in, const int* in_sizes, int n_in,
                              void* d_out, int out_size) {
    const float* x  = (const float*)d_in[0];
    const void*  ei = d_in[1];
    const float* W1 = (const float*)d_in[2];
    const float* b1 = (const float*)d_in[3];
    const float* W2 = (const float*)d_in[4];
    const float* b2 = (const float*)d_in[5];
    float* out = (float*)d_out;

    int M = in_sizes[0] / CIN;     // 50000
    int E = in_sizes[1] / 2;       // 800000
    int n = M * CH;                // 12.8M

    detect_kernel<<<1, 32>>>((const unsigned*)ei, E);

    deg_init_kernel<<<(M + 255) / 256, 256>>>(M);
    deg_acc_kernel<<<(E + 255) / 256, 256>>>(ei, E);
    dinv_kernel<<<(M + 255) / 256, 256>>>(M);

    dim3 g1((M + 127) / 128, CH / 128);
    gemm1_kernel<<<g1, 256>>>(x, W1, M);

    selfloop1_kernel<<<(n + 255) / 256, 256>>>(n);

    long long work1 = (long long)E * 64;
    scatter1_kernel<<<(unsigned)((work1 + 255) / 256), 256>>>(ei, E);

    epilogue_kernel<<<(n + 255) / 256, 256>>>(b1, n);

    gemm2_kernel<<<(M * 32 + 255) / 256, 256>>>(W2, M);

    out_init_kernel<<<(M + 255) / 256, 256>>>(out, b2, M);
    scatter2_kernel<<<(E + 255) / 256, 256>>>(ei, out, E);
}

// round 3
// speedup vs baseline: 1.4945x; 1.4945x over previous
#include <cuda_runtime.h>

// ---------------------------------------------------------------------------
// GCN 2-layer forward on GB300 — round 3: CSR gather (no scatter atomics),
// fused self-loop + bias + ELU + dropout epilogue.
//   h  = x @ W1                                   (50000x512 @ 512x256)
//   a1 = Dinv (A+I) Dinv h ;  a1 += b1 ; ELU ; dropout(p=0.25, jax threefry)
//   p  = a1 @ W2                                  (50000x256 @ 256x1)
//   out= Dinv (A+I) Dinv p + b2
// ---------------------------------------------------------------------------

#define NMAX 50048
#define EMAX 1000000
#define CIN  512
#define CH   256

__device__ int   g_DEGI[NMAX];
__device__ float g_DINV[NMAX];
__device__ int   g_ROWPTR[NMAX + 1];
__device__ int   g_CUR[NMAX];
__device__ int   g_SRC[EMAX];
__device__ float g_NRM[EMAX];
__device__ float g_H  [(size_t)NMAX * CH];
__device__ float g_AGG[(size_t)NMAX * CH];
__device__ float g_P  [NMAX];
__device__ int   g_is64;

// ---------------------------------------------------------------------------
// edge_index dtype detection (int64 vs int32)
// ---------------------------------------------------------------------------
__global__ void detect_kernel(const unsigned* __restrict__ words, int E) {
    if (threadIdx.x == 0 && blockIdx.x == 0) {
        int n = E < 256 ? E : 256;
        unsigned acc = 0u;
        for (int i = 0; i < n; i++) acc |= words[2 * i + 1];
        g_is64 = (acc == 0u) ? 1 : 0;
    }
}

__device__ __forceinline__ int edge_at(const void* ei, int is64, long long idx) {
    if (is64) return (int)((const long long*)ei)[idx];
    return ((const int*)ei)[idx];
}

// ---------------------------------------------------------------------------
// Degree count (int) -> dinv
// ---------------------------------------------------------------------------
__global__ void deg_zero_kernel(int M) {
    int v = blockIdx.x * blockDim.x + threadIdx.x;
    if (v < M) g_DEGI[v] = 0;
}

__global__ void deg_acc_kernel(const void* __restrict__ ei, int E) {
    int e = blockIdx.x * blockDim.x + threadIdx.x;
    if (e >= E) return;
    int d = edge_at(ei, g_is64, (long long)E + e);
    atomicAdd(&g_DEGI[d], 1);
}

__global__ void dinv_kernel(int M) {
    int v = blockIdx.x * blockDim.x + threadIdx.x;
    if (v < M) g_DINV[v] = rsqrtf((float)(g_DEGI[v] + 1));  // +1 self loop
}

// ---------------------------------------------------------------------------
// Single-block exclusive scan of degrees -> ROWPTR, CUR
// ---------------------------------------------------------------------------
__global__ __launch_bounds__(1024) void scan_kernel(int M) {
    const int T = 1024;
    int tid = threadIdx.x;
    int chunk = (M + T - 1) / T;
    int start = tid * chunk;
    int end   = start + chunk; if (end > M) end = M; if (start > M) start = M;

    int s = 0;
    for (int i = start; i < end; i++) s += g_DEGI[i];

    // block-wide inclusive scan of per-thread sums
    int lane = tid & 31, wid = tid >> 5;
    int v = s;
    #pragma unroll
    for (int o = 1; o < 32; o <<= 1) {
        int t = __shfl_up_sync(0xffffffffu, v, o);
        if (lane >= o) v += t;
    }
    __shared__ int wsum[32];
    if (lane == 31) wsum[wid] = v;
    __syncthreads();
    if (wid == 0) {
        int w = wsum[lane];
        #pragma unroll
        for (int o = 1; o < 32; o <<= 1) {
            int t = __shfl_up_sync(0xffffffffu, w, o);
            if (lane >= o) w += t;
        }
        wsum[lane] = w;
    }
    __syncthreads();
    int excl = v - s + (wid > 0 ? wsum[wid - 1] : 0);

    int offset = excl;
    for (int i = start; i < end; i++) {
        int d = g_DEGI[i];
        g_ROWPTR[i] = offset;
        g_CUR[i]    = offset;
        offset += d;
    }
    if (tid == T - 1) g_ROWPTR[M] = offset;
}

// ---------------------------------------------------------------------------
// Counting-sort fill: edges grouped by dst; stores src and norm per slot.
// ---------------------------------------------------------------------------
__global__ void fill_kernel(const void* __restrict__ ei, int E) {
    int e = blockIdx.x * blockDim.x + threadIdx.x;
    if (e >= E) return;
    int is64 = g_is64;
    int s = edge_at(ei, is64, e);
    int d = edge_at(ei, is64, (long long)E + e);
    int pos = atomicAdd(&g_CUR[d], 1);
    g_SRC[pos] = s;
    g_NRM[pos] = g_DINV[s] * g_DINV[d];
}

// ---------------------------------------------------------------------------
// GEMM1: g_H[M,256] = X[M,512] @ W1[512,256]. 128x128x8 tile, 8x8 per thread.
// ---------------------------------------------------------------------------
__global__ __launch_bounds__(256) void gemm1_kernel(
    const float* __restrict__ A, const float* __restrict__ B, int M)
{
    const int K = CIN, N = CH;
    __shared__ float As[8][128];
    __shared__ float Bs[8][128];

    int tid  = threadIdx.x;
    int row0 = blockIdx.x * 128;
    int col0 = blockIdx.y * 128;

    int ty = tid / 16, tx = tid % 16;
    float acc[8][8];
    #pragma unroll
    for (int i = 0; i < 8; i++)
        #pragma unroll
        for (int j = 0; j < 8; j++) acc[i][j] = 0.0f;

    int a_row = tid >> 1;
    int a_k   = (tid & 1) * 4;
    int b_k   = tid >> 5;
    int b_col = (tid & 31) * 4;

    for (int k0 = 0; k0 < K; k0 += 8) {
        float4 av = make_float4(0.f, 0.f, 0.f, 0.f);
        int gr = row0 + a_row;
        if (gr < M) av = *(const float4*)(A + (size_t)gr * K + k0 + a_k);
        As[a_k + 0][a_row] = av.x;
        As[a_k + 1][a_row] = av.y;
        As[a_k + 2][a_row] = av.z;
        As[a_k + 3][a_row] = av.w;

        float4 bv = *(const float4*)(B + (size_t)(k0 + b_k) * N + col0 + b_col);
        *(float4*)&Bs[b_k][b_col] = bv;
        __syncthreads();

        #pragma unroll
        for (int kk = 0; kk < 8; kk++) {
            float ar[8], br[8];
            #pragma unroll
            for (int i = 0; i < 8; i++) ar[i] = As[kk][ty * 8 + i];
            #pragma unroll
            for (int j = 0; j < 8; j++) br[j] = Bs[kk][tx * 8 + j];
            #pragma unroll
            for (int i = 0; i < 8; i++)
                #pragma unroll
                for (int j = 0; j < 8; j++)
                    acc[i][j] += ar[i] * br[j];
        }
        __syncthreads();
    }

    #pragma unroll
    for (int i = 0; i < 8; i++) {
        int gr = row0 + ty * 8 + i;
        if (gr < M) {
            #pragma unroll
            for (int j = 0; j < 8; j += 4) {
                *(float4*)(g_H + (size_t)gr * N + col0 + tx * 8 + j) =
                    make_float4(acc[i][j], acc[i][j+1], acc[i][j+2], acc[i][j+3]);
            }
        }
    }
}

// ---------------------------------------------------------------------------
// threefry2x32, key = (0, 42), partitionable mode: bits = o0 ^ o1
// ---------------------------------------------------------------------------
__device__ __forceinline__ void threefry2x32(unsigned c0, unsigned c1,
                                             unsigned& o0, unsigned& o1) {
    const unsigned ks0 = 0u, ks1 = 42u;
    const unsigned ks2 = 0x1BD11BDAu ^ ks0 ^ ks1;
    unsigned x0 = c0 + ks0;
    unsigned x1 = c1 + ks1;
#define TF_ROUND(r) { x0 += x1; x1 = (x1 << (r)) | (x1 >> (32 - (r))); x1 ^= x0; }
    TF_ROUND(13) TF_ROUND(15) TF_ROUND(26) TF_ROUND(6)
    x0 += ks1; x1 += ks2 + 1u;
    TF_ROUND(17) TF_ROUND(29) TF_ROUND(16) TF_ROUND(24)
    x0 += ks2; x1 += ks0 + 2u;
    TF_ROUND(13) TF_ROUND(15) TF_ROUND(26) TF_ROUND(6)
    x0 += ks0; x1 += ks1 + 3u;
    TF_ROUND(17) TF_ROUND(29) TF_ROUND(16) TF_ROUND(24)
    x0 += ks1; x1 += ks2 + 4u;
    TF_ROUND(13) TF_ROUND(15) TF_ROUND(26) TF_ROUND(6)
    x0 += ks2; x1 += ks0 + 5u;
#undef TF_ROUND
    o0 = x0; o1 = x1;
}

// ---------------------------------------------------------------------------
// Layer-1 aggregate (CSR gather) + fused self-loop + bias + ELU + dropout.
// One block (256 threads = 1 channel each) per node. Edge list staged in SMEM.
// Writes activated result to g_AGG.
// ---------------------------------------------------------------------------
__global__ __launch_bounds__(256) void gather1_kernel(
    const float* __restrict__ b1, int M)
{
    int v = blockIdx.x;
    if (v >= M) return;
    int c = threadIdx.x;

    float dv  = g_DINV[v];
    float acc = dv * dv * g_H[(size_t)v * CH + c];

    int beg = g_ROWPTR[v];
    int end = g_ROWPTR[v + 1];

    __shared__ int   ssrc[128];
    __shared__ float snrm[128];

    for (int base = beg; base < end; base += 128) {
        int cnt = end - base; if (cnt > 128) cnt = 128;
        __syncthreads();
        if (c < cnt) {
            ssrc[c] = g_SRC[base + c];
            snrm[c] = g_NRM[base + c];
        }
        __syncthreads();
        for (int j = 0; j < cnt; j++)
            acc += snrm[j] * g_H[(size_t)ssrc[j] * CH + c];
    }

    // epilogue: bias + ELU + dropout
    unsigned i = (unsigned)v * CH + (unsigned)c;
    unsigned o0, o1;
    threefry2x32(0u, i, o0, o1);
    unsigned bits = o0 ^ o1;
    float u = __uint_as_float((bits >> 9) | 0x3F800000u) - 1.0f;
    float val = acc + b1[c];
    val = val > 0.0f ? val : expm1f(val);
    g_AGG[(size_t)i] = (u < 0.75f) ? val * (1.0f / 0.75f) : 0.0f;
}

// ---------------------------------------------------------------------------
// GEMM2: P[v] = dot(AGG[v,:], W2[:,0]). One warp per node.
// ---------------------------------------------------------------------------
__global__ void gemm2_kernel(const float* __restrict__ W2, int M) {
    int gt   = blockIdx.x * blockDim.x + threadIdx.x;
    int warp = gt >> 5;
    int lane = gt & 31;
    if (warp >= M) return;
    const float4* row = (const float4*)(g_AGG + (size_t)warp * CH);
    const float4* w   = (const float4*)W2;
    float s = 0.0f;
    #pragma unroll
    for (int j = lane; j < CH / 4; j += 32) {
        float4 a = row[j];
        float4 b = w[j];
        s += a.x * b.x + a.y * b.y + a.z * b.z + a.w * b.w;
    }
    #pragma unroll
    for (int o = 16; o > 0; o >>= 1) s += __shfl_xor_sync(0xffffffffu, s, o);
    if (lane == 0) g_P[warp] = s;
}

// ---------------------------------------------------------------------------
// Layer-2 aggregate (CSR gather, scalar). One warp per node.
// ---------------------------------------------------------------------------
__global__ void gather2_kernel(const float* __restrict__ b2,
                               float* __restrict__ out, int M) {
    int gt   = blockIdx.x * blockDim.x + threadIdx.x;
    int warp = gt >> 5;
    int lane = gt & 31;
    if (warp >= M) return;
    int beg = g_ROWPTR[warp];
    int end = g_ROWPTR[warp + 1];
    float s = 0.0f;
    for (int e = beg + lane; e < end; e += 32)
        s += g_NRM[e] * g_P[g_SRC[e]];
    #pragma unroll
    for (int o = 16; o > 0; o >>= 1) s += __shfl_xor_sync(0xffffffffu, s, o);
    if (lane == 0) {
        float dv = g_DINV[warp];
        out[warp] = dv * dv * g_P[warp] + b2[0] + s;
    }
}

// ---------------------------------------------------------------------------
extern "C" void kernel_launch(void* const* d_in, const int* in_sizes, int n_in,
                              void* d_out, int out_size) {
    const float* x  = (const float*)d_in[0];
    const void*  ei = d_in[1];
    const float* W1 = (const float*)d_in[2];
    const float* b1 = (const float*)d_in[3];
    const float* W2 = (const float*)d_in[4];
    const float* b2 = (const float*)d_in[5];
    float* out = (float*)d_out;

    int M = in_sizes[0] / CIN;     // 50000
    int E = in_sizes[1] / 2;       // 800000

    detect_kernel<<<1, 32>>>((const unsigned*)ei, E);

    // CSR build
    deg_zero_kernel<<<(M + 255) / 256, 256>>>(M);
    deg_acc_kernel <<<(E + 255) / 256, 256>>>(ei, E);
    dinv_kernel    <<<(M + 255) / 256, 256>>>(M);
    scan_kernel    <<<1, 1024>>>(M);
    fill_kernel    <<<(E + 255) / 256, 256>>>(ei, E);

    // Layer 1
    dim3 g1((M + 127) / 128, CH / 128);
    gemm1_kernel<<<g1, 256>>>(x, W1, M);
    gather1_kernel<<<M, 256>>>(b1, M);

    // Layer 2
    gemm2_kernel  <<<(M * 32 + 255) / 256, 256>>>(W2, M);
    gather2_kernel<<<(M * 32 + 255) / 256, 256>>>(b2, out, M);
}

// round 5
// speedup vs baseline: 2.5546x; 1.7094x over previous
#include <cuda_runtime.h>
#include <cstdint>

// ---------------------------------------------------------------------------
// GCN 2-layer forward on GB300 — round 5: GEMM1 via mma.sync tf32 (sm_80 PTX,
// works on compute_103 — tcgen05 is NOT available in this toolchain).
//   h  = x @ W1                                   (50000x512 @ 512x256)
//   a1 = Dinv (A+I) Dinv h ;  a1 += b1 ; ELU ; dropout(p=0.25, jax threefry)
//   p  = a1 @ W2                                  (50000x256 @ 256x1)
//   out= Dinv (A+I) Dinv p + b2
// ---------------------------------------------------------------------------

#define NMAX 50048
#define EMAX 1000000
#define CIN  512
#define CH   256

// GEMM1 tiling
#define CTA_M 128
#define CTA_N 128
#define CTA_K 32
#define NSTG  (CIN / CTA_K)          // 16
#define APAD  36                     // A smem row stride (floats)
#define BPAD  136                    // B smem row stride (floats)
#define SM_A_BYTES (CTA_M * APAD * 4)            // 18432
#define SM_B_BYTES (CTA_K * BPAD * 4)            // 17408
#define SM_STAGE   (SM_A_BYTES + SM_B_BYTES)     // 35840
#define SM_TOTAL   (2 * SM_STAGE)                // 71680

__device__ int   g_DEGI[NMAX];
__device__ float g_DINV[NMAX];
__device__ int   g_ROWPTR[NMAX + 1];
__device__ int   g_CUR[NMAX];
__device__ int   g_SRC[EMAX];
__device__ float g_NRM[EMAX];
__device__ float g_H  [(size_t)NMAX * CH];
__device__ float g_AGG[(size_t)NMAX * CH];
__device__ float g_P  [NMAX];
__device__ float g_W1R[(size_t)CIN * CH];   // W1, tf32-rounded, same layout
__device__ int   g_is64;

__device__ __forceinline__ float to_tf32(float x) {
    float r;
    asm("cvt.rna.tf32.f32 %0, %1;" : "=f"(r) : "f"(x));
    return r;
}
__device__ __forceinline__ uint32_t smem_u32(const void* p) {
    uint32_t a;
    asm("{ .reg .u64 t; cvta.to.shared.u64 t, %1; cvt.u32.u64 %0, t; }"
        : "=r"(a) : "l"(p));
    return a;
}
__device__ __forceinline__ void cp_async16(uint32_t dst, const void* src) {
    asm volatile("cp.async.ca.shared.global [%0], [%1], 16;"
                 :: "r"(dst), "l"(src));
}
#define CP_COMMIT() asm volatile("cp.async.commit_group;" ::: "memory")
#define CP_WAIT(n)  asm volatile("cp.async.wait_group %0;" :: "n"(n) : "memory")

__device__ __forceinline__ void mma_tf32(float* c, const float* a, const float* b) {
    asm volatile(
        "mma.sync.aligned.m16n8k8.row.col.f32.tf32.tf32.f32 "
        "{%0,%1,%2,%3}, {%4,%5,%6,%7}, {%8,%9}, {%0,%1,%2,%3};"
        : "+f"(c[0]), "+f"(c[1]), "+f"(c[2]), "+f"(c[3])
        : "r"(__float_as_uint(a[0])), "r"(__float_as_uint(a[1])),
          "r"(__float_as_uint(a[2])), "r"(__float_as_uint(a[3])),
          "r"(__float_as_uint(b[0])), "r"(__float_as_uint(b[1])));
}

// ---------------------------------------------------------------------------
// edge_index dtype detection (int64 vs int32)
// ---------------------------------------------------------------------------
__global__ void detect_kernel(const unsigned* __restrict__ words, int E) {
    if (threadIdx.x == 0 && blockIdx.x == 0) {
        int n = E < 256 ? E : 256;
        unsigned acc = 0u;
        for (int i = 0; i < n; i++) acc |= words[2 * i + 1];
        g_is64 = (acc == 0u) ? 1 : 0;
    }
}
__device__ __forceinline__ int edge_at(const void* ei, int is64, long long idx) {
    if (is64) return (int)((const long long*)ei)[idx];
    return ((const int*)ei)[idx];
}

// ---------------------------------------------------------------------------
// Degree count -> dinv -> CSR (scan + counting-sort fill)
// ---------------------------------------------------------------------------
__global__ void deg_zero_kernel(int M) {
    int v = blockIdx.x * blockDim.x + threadIdx.x;
    if (v < M) g_DEGI[v] = 0;
}
__global__ void deg_acc_kernel(const void* __restrict__ ei, int E) {
    int e = blockIdx.x * blockDim.x + threadIdx.x;
    if (e >= E) return;
    int d = edge_at(ei, g_is64, (long long)E + e);
    atomicAdd(&g_DEGI[d], 1);
}
__global__ void dinv_kernel(int M) {
    int v = blockIdx.x * blockDim.x + threadIdx.x;
    if (v < M) g_DINV[v] = rsqrtf((float)(g_DEGI[v] + 1));
}
__global__ __launch_bounds__(1024) void scan_kernel(int M) {
    const int T = 1024;
    int tid = threadIdx.x;
    int chunk = (M + T - 1) / T;
    int start = tid * chunk;
    int end   = start + chunk; if (end > M) end = M; if (start > M) start = M;
    int s = 0;
    for (int i = start; i < end; i++) s += g_DEGI[i];
    int lane = tid & 31, wid = tid >> 5;
    int v = s;
    #pragma unroll
    for (int o = 1; o < 32; o <<= 1) {
        int t = __shfl_up_sync(0xffffffffu, v, o);
        if (lane >= o) v += t;
    }
    __shared__ int wsum[32];
    if (lane == 31) wsum[wid] = v;
    __syncthreads();
    if (wid == 0) {
        int w = wsum[lane];
        #pragma unroll
        for (int o = 1; o < 32; o <<= 1) {
            int t = __shfl_up_sync(0xffffffffu, w, o);
            if (lane >= o) w += t;
        }
        wsum[lane] = w;
    }
    __syncthreads();
    int excl = v - s + (wid > 0 ? wsum[wid - 1] : 0);
    int offset = excl;
    for (int i = start; i < end; i++) {
        int d = g_DEGI[i];
        g_ROWPTR[i] = offset;
        g_CUR[i]    = offset;
        offset += d;
    }
    if (tid == T - 1) g_ROWPTR[M] = offset;
}
__global__ void fill_kernel(const void* __restrict__ ei, int E) {
    int e = blockIdx.x * blockDim.x + threadIdx.x;
    if (e >= E) return;
    int is64 = g_is64;
    int s = edge_at(ei, is64, e);
    int d = edge_at(ei, is64, (long long)E + e);
    int pos = atomicAdd(&g_CUR[d], 1);
    g_SRC[pos] = s;
    g_NRM[pos] = g_DINV[s] * g_DINV[d];
}

// ---------------------------------------------------------------------------
// W1 tf32 pre-round (same layout [512][256])
// ---------------------------------------------------------------------------
__global__ void w1r_kernel(const float* __restrict__ W1) {
    int idx = blockIdx.x * blockDim.x + threadIdx.x;
    if (idx < CIN * CH) g_W1R[idx] = to_tf32(W1[idx]);
}

// ---------------------------------------------------------------------------
// GEMM1: g_H = X @ W1 via mma.sync.m16n8k8 tf32.
// CTA 128x128, 8 warps (4m x 2n), warp tile 32x64. cp.async double buffer.
// ---------------------------------------------------------------------------
__global__ __launch_bounds__(256, 2) void gemm1_mma_kernel(
    const float* __restrict__ X, int M)
{
    extern __shared__ float sm[];
    uint32_t smb = smem_u32(sm);

    int tid  = threadIdx.x;
    int wid  = tid >> 5;
    int lane = tid & 31;
    int gid  = lane >> 2;      // 0..7
    int tig  = lane & 3;       // 0..3
    int wm   = wid >> 1;       // 0..3
    int wn   = wid & 1;        // 0..1

    int m0 = blockIdx.x * CTA_M;
    int n0 = blockIdx.y * CTA_N;

    float acc[2][8][4];
    #pragma unroll
    for (int i = 0; i < 2; i++)
        #pragma unroll
        for (int j = 0; j < 8; j++)
            #pragma unroll
            for (int k = 0; k < 4; k++) acc[i][j][k] = 0.0f;

    // cp.async issue for one stage
    auto issue = [&](int s, int buf) {
        uint32_t baseA = smb + buf * SM_STAGE;
        uint32_t baseB = baseA + SM_A_BYTES;
        #pragma unroll
        for (int it = 0; it < 4; it++) {
            int id  = it * 256 + tid;
            // A chunk: row (0..127), kq (0..7 float4 within CTA_K)
            int ar = id >> 3, akq = id & 7;
            int grow = m0 + ar; if (grow > M - 1) grow = M - 1;
            cp_async16(baseA + (uint32_t)(ar * APAD + akq * 4) * 4,
                       X + (size_t)grow * CIN + s * CTA_K + akq * 4);
            // B chunk: krow (0..31), nc (0..31 float4 within CTA_N)
            int bk = id >> 5, bnc = id & 31;
            cp_async16(baseB + (uint32_t)(bk * BPAD + bnc * 4) * 4,
                       g_W1R + (size_t)(s * CTA_K + bk) * CH + n0 + bnc * 4);
        }
    };

    issue(0, 0);
    CP_COMMIT();

    for (int s = 0; s < NSTG; s++) {
        int buf = s & 1;
        if (s + 1 < NSTG) {
            issue(s + 1, buf ^ 1);
            CP_COMMIT();
            CP_WAIT(1);
        } else {
            CP_WAIT(0);
        }
        __syncthreads();

        const float* sA = sm + buf * (SM_STAGE / 4);
        const float* sB = sA + (SM_A_BYTES / 4);

        #pragma unroll
        for (int ks = 0; ks < 4; ks++) {
            float a[2][4];
            #pragma unroll
            for (int mt = 0; mt < 2; mt++) {
                int r = wm * 32 + mt * 16 + gid;
                int c = ks * 8 + tig;
                a[mt][0] = to_tf32(sA[r * APAD + c]);
                a[mt][1] = to_tf32(sA[(r + 8) * APAD + c]);
                a[mt][2] = to_tf32(sA[r * APAD + c + 4]);
                a[mt][3] = to_tf32(sA[(r + 8) * APAD + c + 4]);
            }
            float b[8][2];
            #pragma unroll
            for (int nt = 0; nt < 8; nt++) {
                int kk = ks * 8 + tig;
                int cc = wn * 64 + nt * 8 + gid;
                b[nt][0] = sB[kk * BPAD + cc];
                b[nt][1] = sB[(kk + 4) * BPAD + cc];
            }
            #pragma unroll
            for (int mt = 0; mt < 2; mt++)
                #pragma unroll
                for (int nt = 0; nt < 8; nt++)
                    mma_tf32(acc[mt][nt], a[mt], b[nt]);
        }
        __syncthreads();
    }

    // Epilogue
    #pragma unroll
    for (int mt = 0; mt < 2; mt++) {
        int r0 = m0 + wm * 32 + mt * 16 + gid;
        #pragma unroll
        for (int nt = 0; nt < 8; nt++) {
            int c = n0 + wn * 64 + nt * 8 + 2 * tig;
            if (r0 < M)
                *(float2*)(g_H + (size_t)r0 * CH + c) =
                    make_float2(acc[mt][nt][0], acc[mt][nt][1]);
            if (r0 + 8 < M)
                *(float2*)(g_H + (size_t)(r0 + 8) * CH + c) =
                    make_float2(acc[mt][nt][2], acc[mt][nt][3]);
        }
    }
}

// ---------------------------------------------------------------------------
// threefry2x32, key = (0, 42), partitionable mode: bits = o0 ^ o1
// ---------------------------------------------------------------------------
__device__ __forceinline__ void threefry2x32(unsigned c0, unsigned c1,
                                             unsigned& o0, unsigned& o1) {
    const unsigned ks0 = 0u, ks1 = 42u;
    const unsigned ks2 = 0x1BD11BDAu ^ ks0 ^ ks1;
    unsigned x0 = c0 + ks0;
    unsigned x1 = c1 + ks1;
#define TF_ROUND(r) { x0 += x1; x1 = (x1 << (r)) | (x1 >> (32 - (r))); x1 ^= x0; }
    TF_ROUND(13) TF_ROUND(15) TF_ROUND(26) TF_ROUND(6)
    x0 += ks1; x1 += ks2 + 1u;
    TF_ROUND(17) TF_ROUND(29) TF_ROUND(16) TF_ROUND(24)
    x0 += ks2; x1 += ks0 + 2u;
    TF_ROUND(13) TF_ROUND(15) TF_ROUND(26) TF_ROUND(6)
    x0 += ks0; x1 += ks1 + 3u;
    TF_ROUND(17) TF_ROUND(29) TF_ROUND(16) TF_ROUND(24)
    x0 += ks1; x1 += ks2 + 4u;
    TF_ROUND(13) TF_ROUND(15) TF_ROUND(26) TF_ROUND(6)
    x0 += ks2; x1 += ks0 + 5u;
#undef TF_ROUND
    o0 = x0; o1 = x1;
}

// ---------------------------------------------------------------------------
// Layer-1 aggregate (CSR gather) + fused self-loop + bias + ELU + dropout.
// ---------------------------------------------------------------------------
__global__ __launch_bounds__(256) void gather1_kernel(
    const float* __restrict__ b1, int M)
{
    int v = blockIdx.x;
    if (v >= M) return;
    int c = threadIdx.x;

    float dv  = g_DINV[v];
    float acc = dv * dv * g_H[(size_t)v * CH + c];

    int beg = g_ROWPTR[v];
    int end = g_ROWPTR[v + 1];

    __shared__ int   ssrc[128];
    __shared__ float snrm[128];

    for (int base = beg; base < end; base += 128) {
        int cnt = end - base; if (cnt > 128) cnt = 128;
        __syncthreads();
        if (c < cnt) {
            ssrc[c] = g_SRC[base + c];
            snrm[c] = g_NRM[base + c];
        }
        __syncthreads();
        for (int j = 0; j < cnt; j++)
            acc += snrm[j] * g_H[(size_t)ssrc[j] * CH + c];
    }

    unsigned i = (unsigned)v * CH + (unsigned)c;
    unsigned o0, o1;
    threefry2x32(0u, i, o0, o1);
    unsigned bits = o0 ^ o1;
    float u = __uint_as_float((bits >> 9) | 0x3F800000u) - 1.0f;
    float val = acc + b1[c];
    val = val > 0.0f ? val : expm1f(val);
    g_AGG[(size_t)i] = (u < 0.75f) ? val * (1.0f / 0.75f) : 0.0f;
}

// ---------------------------------------------------------------------------
// GEMM2: P[v] = dot(AGG[v,:], W2[:,0]). One warp per node.
// ---------------------------------------------------------------------------
__global__ void gemm2_kernel(const float* __restrict__ W2, int M) {
    int gt   = blockIdx.x * blockDim.x + threadIdx.x;
    int warp = gt >> 5;
    int lane = gt & 31;
    if (warp >= M) return;
    const float4* row = (const float4*)(g_AGG + (size_t)warp * CH);
    const float4* w   = (const float4*)W2;
    float s = 0.0f;
    #pragma unroll
    for (int j = lane; j < CH / 4; j += 32) {
        float4 a = row[j];
        float4 b = w[j];
        s += a.x * b.x + a.y * b.y + a.z * b.z + a.w * b.w;
    }
    #pragma unroll
    for (int o = 16; o > 0; o >>= 1) s += __shfl_xor_sync(0xffffffffu, s, o);
    if (lane == 0) g_P[warp] = s;
}

// ---------------------------------------------------------------------------
// Layer-2 aggregate (CSR gather, scalar). One warp per node.
// ---------------------------------------------------------------------------
__global__ void gather2_kernel(const float* __restrict__ b2,
                               float* __restrict__ out, int M) {
    int gt   = blockIdx.x * blockDim.x + threadIdx.x;
    int warp = gt >> 5;
    int lane = gt & 31;
    if (warp >= M) return;
    int beg = g_ROWPTR[warp];
    int end = g_ROWPTR[warp + 1];
    float s = 0.0f;
    for (int e = beg + lane; e < end; e += 32)
        s += g_NRM[e] * g_P[g_SRC[e]];
    #pragma unroll
    for (int o = 16; o > 0; o >>= 1) s += __shfl_xor_sync(0xffffffffu, s, o);
    if (lane == 0) {
        float dv = g_DINV[warp];
        out[warp] = dv * dv * g_P[warp] + b2[0] + s;
    }
}

// ---------------------------------------------------------------------------
extern "C" void kernel_launch(void* const* d_in, const int* in_sizes, int n_in,
                              void* d_out, int out_size) {
    const float* x  = (const float*)d_in[0];
    const void*  ei = d_in[1];
    const float* W1 = (const float*)d_in[2];
    const float* b1 = (const float*)d_in[3];
    const float* W2 = (const float*)d_in[4];
    const float* b2 = (const float*)d_in[5];
    float* out = (float*)d_out;

    int M = in_sizes[0] / CIN;     // 50000
    int E = in_sizes[1] / 2;       // 800000

    static int cfg = 0;
    if (!cfg) {
        cudaFuncSetAttribute(gemm1_mma_kernel,
                             cudaFuncAttributeMaxDynamicSharedMemorySize, SM_TOTAL);
        cfg = 1;
    }

    detect_kernel<<<1, 32>>>((const unsigned*)ei, E);

    // CSR build
    deg_zero_kernel<<<(M + 255) / 256, 256>>>(M);
    deg_acc_kernel <<<(E + 255) / 256, 256>>>(ei, E);
    dinv_kernel    <<<(M + 255) / 256, 256>>>(M);
    scan_kernel    <<<1, 1024>>>(M);
    fill_kernel    <<<(E + 255) / 256, 256>>>(ei, E);

    // Layer 1
    w1r_kernel<<<(CIN * CH + 255) / 256, 256>>>(W1);
    dim3 g1((M + CTA_M - 1) / CTA_M, CH / CTA_N);  // (391, 2)
    gemm1_mma_kernel<<<g1, 256, SM_TOTAL>>>(x, M);
    gather1_kernel<<<M, 256>>>(b1, M);

    // Layer 2
    gemm2_kernel  <<<(M * 32 + 255) / 256, 256>>>(W2, M);
    gather2_kernel<<<(M * 32 + 255) / 256, 256>>>(b2, out, M);
}

// round 6
// speedup vs baseline: 2.6172x; 1.0245x over previous
#include <cuda_runtime.h>
#include <cstdint>

// ---------------------------------------------------------------------------
// GCN 2-layer forward on GB300 — round 6: GEMM2 fused into gather1 epilogue.
//   h  = x @ W1                 (mma.sync tf32, 50000x512 @ 512x256)
//   a1 = Dinv (A+I) Dinv h ; +b1 ; ELU ; dropout(p=0.25, jax threefry)
//   p  = a1 @ W2                (fused: block dot-product in gather1)
//   out= Dinv (A+I) Dinv p + b2
// ---------------------------------------------------------------------------

#define NMAX 50048
#define EMAX 1000000
#define CIN  512
#define CH   256

// GEMM1 tiling
#define CTA_M 128
#define CTA_N 128
#define CTA_K 32
#define NSTG  (CIN / CTA_K)          // 16
#define APAD  36                     // A smem row stride (floats)
#define BPAD  136                    // B smem row stride (floats)
#define SM_A_BYTES (CTA_M * APAD * 4)            // 18432
#define SM_B_BYTES (CTA_K * BPAD * 4)            // 17408
#define SM_STAGE   (SM_A_BYTES + SM_B_BYTES)     // 35840
#define SM_TOTAL   (2 * SM_STAGE)                // 71680

__device__ int   g_DEGI[NMAX];
__device__ float g_DINV[NMAX];
__device__ int   g_ROWPTR[NMAX + 1];
__device__ int   g_CUR[NMAX];
__device__ int   g_SRC[EMAX];
__device__ float g_NRM[EMAX];
__device__ float g_H  [(size_t)NMAX * CH];
__device__ float g_P  [NMAX];
__device__ float g_W1R[(size_t)CIN * CH];   // W1, tf32-rounded, same layout
__device__ int   g_is64;

__device__ __forceinline__ float to_tf32(float x) {
    float r;
    asm("cvt.rna.tf32.f32 %0, %1;" : "=f"(r) : "f"(x));
    return r;
}
__device__ __forceinline__ uint32_t smem_u32(const void* p) {
    uint32_t a;
    asm("{ .reg .u64 t; cvta.to.shared.u64 t, %1; cvt.u32.u64 %0, t; }"
        : "=r"(a) : "l"(p));
    return a;
}
__device__ __forceinline__ void cp_async16(uint32_t dst, const void* src) {
    asm volatile("cp.async.ca.shared.global [%0], [%1], 16;"
                 :: "r"(dst), "l"(src));
}
#define CP_COMMIT() asm volatile("cp.async.commit_group;" ::: "memory")
#define CP_WAIT(n)  asm volatile("cp.async.wait_group %0;" :: "n"(n) : "memory")

__device__ __forceinline__ void mma_tf32(float* c, const float* a, const float* b) {
    asm volatile(
        "mma.sync.aligned.m16n8k8.row.col.f32.tf32.tf32.f32 "
        "{%0,%1,%2,%3}, {%4,%5,%6,%7}, {%8,%9}, {%0,%1,%2,%3};"
        : "+f"(c[0]), "+f"(c[1]), "+f"(c[2]), "+f"(c[3])
        : "r"(__float_as_uint(a[0])), "r"(__float_as_uint(a[1])),
          "r"(__float_as_uint(a[2])), "r"(__float_as_uint(a[3])),
          "r"(__float_as_uint(b[0])), "r"(__float_as_uint(b[1])));
}

// ---------------------------------------------------------------------------
// edge_index dtype detection (int64 vs int32)
// ---------------------------------------------------------------------------
__global__ void detect_kernel(const unsigned* __restrict__ words, int E) {
    if (threadIdx.x == 0 && blockIdx.x == 0) {
        int n = E < 256 ? E : 256;
        unsigned acc = 0u;
        for (int i = 0; i < n; i++) acc |= words[2 * i + 1];
        g_is64 = (acc == 0u) ? 1 : 0;
    }
}
__device__ __forceinline__ int edge_at(const void* ei, int is64, long long idx) {
    if (is64) return (int)((const long long*)ei)[idx];
    return ((const int*)ei)[idx];
}

// ---------------------------------------------------------------------------
// Degree count -> dinv -> CSR (scan + counting-sort fill)
// ---------------------------------------------------------------------------
__global__ void deg_zero_kernel(int M) {
    int v = blockIdx.x * blockDim.x + threadIdx.x;
    if (v < M) g_DEGI[v] = 0;
}
__global__ void deg_acc_kernel(const void* __restrict__ ei, int E) {
    int e = blockIdx.x * blockDim.x + threadIdx.x;
    if (e >= E) return;
    int d = edge_at(ei, g_is64, (long long)E + e);
    atomicAdd(&g_DEGI[d], 1);
}
__global__ void dinv_kernel(int M) {
    int v = blockIdx.x * blockDim.x + threadIdx.x;
    if (v < M) g_DINV[v] = rsqrtf((float)(g_DEGI[v] + 1));
}
__global__ __launch_bounds__(1024) void scan_kernel(int M) {
    const int T = 1024;
    int tid = threadIdx.x;
    int chunk = (M + T - 1) / T;
    int start = tid * chunk;
    int end   = start + chunk; if (end > M) end = M; if (start > M) start = M;
    int s = 0;
    for (int i = start; i < end; i++) s += g_DEGI[i];
    int lane = tid & 31, wid = tid >> 5;
    int v = s;
    #pragma unroll
    for (int o = 1; o < 32; o <<= 1) {
        int t = __shfl_up_sync(0xffffffffu, v, o);
        if (lane >= o) v += t;
    }
    __shared__ int wsum[32];
    if (lane == 31) wsum[wid] = v;
    __syncthreads();
    if (wid == 0) {
        int w = wsum[lane];
        #pragma unroll
        for (int o = 1; o < 32; o <<= 1) {
            int t = __shfl_up_sync(0xffffffffu, w, o);
            if (lane >= o) w += t;
        }
        wsum[lane] = w;
    }
    __syncthreads();
    int excl = v - s + (wid > 0 ? wsum[wid - 1] : 0);
    int offset = excl;
    for (int i = start; i < end; i++) {
        int d = g_DEGI[i];
        g_ROWPTR[i] = offset;
        g_CUR[i]    = offset;
        offset += d;
    }
    if (tid == T - 1) g_ROWPTR[M] = offset;
}
__global__ void fill_kernel(const void* __restrict__ ei, int E) {
    int e = blockIdx.x * blockDim.x + threadIdx.x;
    if (e >= E) return;
    int is64 = g_is64;
    int s = edge_at(ei, is64, e);
    int d = edge_at(ei, is64, (long long)E + e);
    int pos = atomicAdd(&g_CUR[d], 1);
    g_SRC[pos] = s;
    g_NRM[pos] = g_DINV[s] * g_DINV[d];
}

// ---------------------------------------------------------------------------
// W1 tf32 pre-round (same layout [512][256])
// ---------------------------------------------------------------------------
__global__ void w1r_kernel(const float* __restrict__ W1) {
    int idx = blockIdx.x * blockDim.x + threadIdx.x;
    if (idx < CIN * CH) g_W1R[idx] = to_tf32(W1[idx]);
}

// ---------------------------------------------------------------------------
// GEMM1: g_H = X @ W1 via mma.sync.m16n8k8 tf32.
// CTA 128x128, 8 warps (4m x 2n), warp tile 32x64. cp.async double buffer.
// ---------------------------------------------------------------------------
__global__ __launch_bounds__(256, 2) void gemm1_mma_kernel(
    const float* __restrict__ X, int M)
{
    extern __shared__ float sm[];
    uint32_t smb = smem_u32(sm);

    int tid  = threadIdx.x;
    int wid  = tid >> 5;
    int lane = tid & 31;
    int gid  = lane >> 2;      // 0..7
    int tig  = lane & 3;       // 0..3
    int wm   = wid >> 1;       // 0..3
    int wn   = wid & 1;        // 0..1

    int m0 = blockIdx.x * CTA_M;
    int n0 = blockIdx.y * CTA_N;

    float acc[2][8][4];
    #pragma unroll
    for (int i = 0; i < 2; i++)
        #pragma unroll
        for (int j = 0; j < 8; j++)
            #pragma unroll
            for (int k = 0; k < 4; k++) acc[i][j][k] = 0.0f;

    auto issue = [&](int s, int buf) {
        uint32_t baseA = smb + buf * SM_STAGE;
        uint32_t baseB = baseA + SM_A_BYTES;
        #pragma unroll
        for (int it = 0; it < 4; it++) {
            int id  = it * 256 + tid;
            int ar = id >> 3, akq = id & 7;
            int grow = m0 + ar; if (grow > M - 1) grow = M - 1;
            cp_async16(baseA + (uint32_t)(ar * APAD + akq * 4) * 4,
                       X + (size_t)grow * CIN + s * CTA_K + akq * 4);
            int bk = id >> 5, bnc = id & 31;
            cp_async16(baseB + (uint32_t)(bk * BPAD + bnc * 4) * 4,
                       g_W1R + (size_t)(s * CTA_K + bk) * CH + n0 + bnc * 4);
        }
    };

    issue(0, 0);
    CP_COMMIT();

    for (int s = 0; s < NSTG; s++) {
        int buf = s & 1;
        if (s + 1 < NSTG) {
            issue(s + 1, buf ^ 1);
            CP_COMMIT();
            CP_WAIT(1);
        } else {
            CP_WAIT(0);
        }
        __syncthreads();

        const float* sA = sm + buf * (SM_STAGE / 4);
        const float* sB = sA + (SM_A_BYTES / 4);

        #pragma unroll
        for (int ks = 0; ks < 4; ks++) {
            float a[2][4];
            #pragma unroll
            for (int mt = 0; mt < 2; mt++) {
                int r = wm * 32 + mt * 16 + gid;
                int c = ks * 8 + tig;
                a[mt][0] = to_tf32(sA[r * APAD + c]);
                a[mt][1] = to_tf32(sA[(r + 8) * APAD + c]);
                a[mt][2] = to_tf32(sA[r * APAD + c + 4]);
                a[mt][3] = to_tf32(sA[(r + 8) * APAD + c + 4]);
            }
            float b[8][2];
            #pragma unroll
            for (int nt = 0; nt < 8; nt++) {
                int kk = ks * 8 + tig;
                int cc = wn * 64 + nt * 8 + gid;
                b[nt][0] = sB[kk * BPAD + cc];
                b[nt][1] = sB[(kk + 4) * BPAD + cc];
            }
            #pragma unroll
            for (int mt = 0; mt < 2; mt++)
                #pragma unroll
                for (int nt = 0; nt < 8; nt++)
                    mma_tf32(acc[mt][nt], a[mt], b[nt]);
        }
        __syncthreads();
    }

    #pragma unroll
    for (int mt = 0; mt < 2; mt++) {
        int r0 = m0 + wm * 32 + mt * 16 + gid;
        #pragma unroll
        for (int nt = 0; nt < 8; nt++) {
            int c = n0 + wn * 64 + nt * 8 + 2 * tig;
            if (r0 < M)
                *(float2*)(g_H + (size_t)r0 * CH + c) =
                    make_float2(acc[mt][nt][0], acc[mt][nt][1]);
            if (r0 + 8 < M)
                *(float2*)(g_H + (size_t)(r0 + 8) * CH + c) =
                    make_float2(acc[mt][nt][2], acc[mt][nt][3]);
        }
    }
}

// ---------------------------------------------------------------------------
// threefry2x32, key = (0, 42), partitionable mode: bits = o0 ^ o1
// ---------------------------------------------------------------------------
__device__ __forceinline__ void threefry2x32(unsigned c0, unsigned c1,
                                             unsigned& o0, unsigned& o1) {
    const unsigned ks0 = 0u, ks1 = 42u;
    const unsigned ks2 = 0x1BD11BDAu ^ ks0 ^ ks1;
    unsigned x0 = c0 + ks0;
    unsigned x1 = c1 + ks1;
#define TF_ROUND(r) { x0 += x1; x1 = (x1 << (r)) | (x1 >> (32 - (r))); x1 ^= x0; }
    TF_ROUND(13) TF_ROUND(15) TF_ROUND(26) TF_ROUND(6)
    x0 += ks1; x1 += ks2 + 1u;
    TF_ROUND(17) TF_ROUND(29) TF_ROUND(16) TF_ROUND(24)
    x0 += ks2; x1 += ks0 + 2u;
    TF_ROUND(13) TF_ROUND(15) TF_ROUND(26) TF_ROUND(6)
    x0 += ks0; x1 += ks1 + 3u;
    TF_ROUND(17) TF_ROUND(29) TF_ROUND(16) TF_ROUND(24)
    x0 += ks1; x1 += ks2 + 4u;
    TF_ROUND(13) TF_ROUND(15) TF_ROUND(26) TF_ROUND(6)
    x0 += ks2; x1 += ks0 + 5u;
#undef TF_ROUND
    o0 = x0; o1 = x1;
}

// ---------------------------------------------------------------------------
// Layer-1 aggregate (CSR gather) + fused self-loop + bias + ELU + dropout
// + fused GEMM2 (block dot product with W2) -> writes g_P[v] only.
// ---------------------------------------------------------------------------
__global__ __launch_bounds__(256) void gather1_kernel(
    const float* __restrict__ b1, const float* __restrict__ W2, int M)
{
    int v = blockIdx.x;
    if (v >= M) return;
    int c = threadIdx.x;

    float dv  = g_DINV[v];
    float acc = dv * dv * g_H[(size_t)v * CH + c];

    int beg = g_ROWPTR[v];
    int end = g_ROWPTR[v + 1];

    __shared__ int   ssrc[128];
    __shared__ float snrm[128];

    for (int base = beg; base < end; base += 128) {
        int cnt = end - base; if (cnt > 128) cnt = 128;
        __syncthreads();
        if (c < cnt) {
            ssrc[c] = g_SRC[base + c];
            snrm[c] = g_NRM[base + c];
        }
        __syncthreads();
        for (int j = 0; j < cnt; j++)
            acc += snrm[j] * g_H[(size_t)ssrc[j] * CH + c];
    }

    // epilogue: bias + ELU + dropout
    unsigned i = (unsigned)v * CH + (unsigned)c;
    unsigned o0, o1;
    threefry2x32(0u, i, o0, o1);
    unsigned bits = o0 ^ o1;
    float u = __uint_as_float((bits >> 9) | 0x3F800000u) - 1.0f;
    float val = acc + b1[c];
    val = val > 0.0f ? val : expm1f(val);
    float act = (u < 0.75f) ? val * (1.0f / 0.75f) : 0.0f;

    // fused GEMM2: P[v] = sum_c act[c] * W2[c]
    float t = act * W2[c];
    int lane = c & 31, wrp = c >> 5;
    #pragma unroll
    for (int o = 16; o > 0; o >>= 1) t += __shfl_xor_sync(0xffffffffu, t, o);
    __shared__ float wred[8];
    if (lane == 0) wred[wrp] = t;
    __syncthreads();
    if (c == 0) {
        float s = 0.0f;
        #pragma unroll
        for (int w = 0; w < 8; w++) s += wred[w];
        g_P[v] = s;
    }
}

// ---------------------------------------------------------------------------
// Layer-2 aggregate (CSR gather, scalar). One warp per node.
// ---------------------------------------------------------------------------
__global__ void gather2_kernel(const float* __restrict__ b2,
                               float* __restrict__ out, int M) {
    int gt   = blockIdx.x * blockDim.x + threadIdx.x;
    int warp = gt >> 5;
    int lane = gt & 31;
    if (warp >= M) return;
    int beg = g_ROWPTR[warp];
    int end = g_ROWPTR[warp + 1];
    float s = 0.0f;
    for (int e = beg + lane; e < end; e += 32)
        s += g_NRM[e] * g_P[g_SRC[e]];
    #pragma unroll
    for (int o = 16; o > 0; o >>= 1) s += __shfl_xor_sync(0xffffffffu, s, o);
    if (lane == 0) {
        float dv = g_DINV[warp];
        out[warp] = dv * dv * g_P[warp] + b2[0] + s;
    }
}

// ---------------------------------------------------------------------------
extern "C" void kernel_launch(void* const* d_in, const int* in_sizes, int n_in,
                              void* d_out, int out_size) {
    const float* x  = (const float*)d_in[0];
    const void*  ei = d_in[1];
    const float* W1 = (const float*)d_in[2];
    const float* b1 = (const float*)d_in[3];
    const float* W2 = (const float*)d_in[4];
    const float* b2 = (const float*)d_in[5];
    float* out = (float*)d_out;

    int M = in_sizes[0] / CIN;     // 50000
    int E = in_sizes[1] / 2;       // 800000

    static int cfg = 0;
    if (!cfg) {
        cudaFuncSetAttribute(gemm1_mma_kernel,
                             cudaFuncAttributeMaxDynamicSharedMemorySize, SM_TOTAL);
        cfg = 1;
    }

    detect_kernel<<<1, 32>>>((const unsigned*)ei, E);

    // CSR build
    deg_zero_kernel<<<(M + 255) / 256, 256>>>(M);
    deg_acc_kernel <<<(E + 255) / 256, 256>>>(ei, E);
    dinv_kernel    <<<(M + 255) / 256, 256>>>(M);
    scan_kernel    <<<1, 1024>>>(M);
    fill_kernel    <<<(E + 255) / 256, 256>>>(ei, E);

    // Layer 1 (+ fused GEMM2)
    w1r_kernel<<<(CIN * CH + 255) / 256, 256>>>(W1);
    dim3 g1((M + CTA_M - 1) / CTA_M, CH / CTA_N);  // (391, 2)
    gemm1_mma_kernel<<<g1, 256, SM_TOTAL>>>(x, M);
    gather1_kernel<<<M, 256>>>(b1, W2, M);

    // Layer 2
    gather2_kernel<<<(M * 32 + 255) / 256, 256>>>(b2, out, M);
}

// round 7
// speedup vs baseline: 3.1718x; 1.2119x over previous
#include <cuda_runtime.h>
#include <cstdint>

// ---------------------------------------------------------------------------
// GCN 2-layer forward on GB300 — round 7: gather1 restructured
// (4 nodes/block, float4/thread, unrolled direct edge loads, no staging).
//   h  = x @ W1                 (mma.sync tf32, 50000x512 @ 512x256)
//   a1 = Dinv (A+I) Dinv h ; +b1 ; ELU ; dropout(p=0.25, jax threefry)
//   p  = a1 @ W2                (fused: group dot-product in gather1)
//   out= Dinv (A+I) Dinv p + b2
// ---------------------------------------------------------------------------

#define NMAX 50048
#define EMAX 1000000
#define CIN  512
#define CH   256

// GEMM1 tiling
#define CTA_M 128
#define CTA_N 128
#define CTA_K 32
#define NSTG  (CIN / CTA_K)          // 16
#define APAD  36
#define BPAD  136
#define SM_A_BYTES (CTA_M * APAD * 4)
#define SM_B_BYTES (CTA_K * BPAD * 4)
#define SM_STAGE   (SM_A_BYTES + SM_B_BYTES)
#define SM_TOTAL   (2 * SM_STAGE)

__device__ int   g_DEGI[NMAX];
__device__ float g_DINV[NMAX];
__device__ int   g_ROWPTR[NMAX + 1];
__device__ int   g_CUR[NMAX];
__device__ int   g_SRC[EMAX];
__device__ float g_NRM[EMAX];
__device__ float g_H  [(size_t)NMAX * CH];
__device__ float g_P  [NMAX];
__device__ float g_W1R[(size_t)CIN * CH];
__device__ int   g_is64;

__device__ __forceinline__ float to_tf32(float x) {
    float r;
    asm("cvt.rna.tf32.f32 %0, %1;" : "=f"(r) : "f"(x));
    return r;
}
__device__ __forceinline__ uint32_t smem_u32(const void* p) {
    uint32_t a;
    asm("{ .reg .u64 t; cvta.to.shared.u64 t, %1; cvt.u32.u64 %0, t; }"
        : "=r"(a) : "l"(p));
    return a;
}
__device__ __forceinline__ void cp_async16(uint32_t dst, const void* src) {
    asm volatile("cp.async.ca.shared.global [%0], [%1], 16;"
                 :: "r"(dst), "l"(src));
}
#define CP_COMMIT() asm volatile("cp.async.commit_group;" ::: "memory")
#define CP_WAIT(n)  asm volatile("cp.async.wait_group %0;" :: "n"(n) : "memory")

__device__ __forceinline__ void mma_tf32(float* c, const float* a, const float* b) {
    asm volatile(
        "mma.sync.aligned.m16n8k8.row.col.f32.tf32.tf32.f32 "
        "{%0,%1,%2,%3}, {%4,%5,%6,%7}, {%8,%9}, {%0,%1,%2,%3};"
        : "+f"(c[0]), "+f"(c[1]), "+f"(c[2]), "+f"(c[3])
        : "r"(__float_as_uint(a[0])), "r"(__float_as_uint(a[1])),
          "r"(__float_as_uint(a[2])), "r"(__float_as_uint(a[3])),
          "r"(__float_as_uint(b[0])), "r"(__float_as_uint(b[1])));
}

// ---------------------------------------------------------------------------
__global__ void detect_kernel(const unsigned* __restrict__ words, int E) {
    if (threadIdx.x == 0 && blockIdx.x == 0) {
        int n = E < 256 ? E : 256;
        unsigned acc = 0u;
        for (int i = 0; i < n; i++) acc |= words[2 * i + 1];
        g_is64 = (acc == 0u) ? 1 : 0;
    }
}
__device__ __forceinline__ int edge_at(const void* ei, int is64, long long idx) {
    if (is64) return (int)((const long long*)ei)[idx];
    return ((const int*)ei)[idx];
}

// ---------------------------------------------------------------------------
__global__ void deg_zero_kernel(int M) {
    int v = blockIdx.x * blockDim.x + threadIdx.x;
    if (v < M) g_DEGI[v] = 0;
}
__global__ void deg_acc_kernel(const void* __restrict__ ei, int E) {
    int e = blockIdx.x * blockDim.x + threadIdx.x;
    if (e >= E) return;
    int d = edge_at(ei, g_is64, (long long)E + e);
    atomicAdd(&g_DEGI[d], 1);
}
__global__ void dinv_kernel(int M) {
    int v = blockIdx.x * blockDim.x + threadIdx.x;
    if (v < M) g_DINV[v] = rsqrtf((float)(g_DEGI[v] + 1));
}
__global__ __launch_bounds__(1024) void scan_kernel(int M) {
    const int T = 1024;
    int tid = threadIdx.x;
    int chunk = (M + T - 1) / T;
    int start = tid * chunk;
    int end   = start + chunk; if (end > M) end = M; if (start > M) start = M;
    int s = 0;
    for (int i = start; i < end; i++) s += g_DEGI[i];
    int lane = tid & 31, wid = tid >> 5;
    int v = s;
    #pragma unroll
    for (int o = 1; o < 32; o <<= 1) {
        int t = __shfl_up_sync(0xffffffffu, v, o);
        if (lane >= o) v += t;
    }
    __shared__ int wsum[32];
    if (lane == 31) wsum[wid] = v;
    __syncthreads();
    if (wid == 0) {
        int w = wsum[lane];
        #pragma unroll
        for (int o = 1; o < 32; o <<= 1) {
            int t = __shfl_up_sync(0xffffffffu, w, o);
            if (lane >= o) w += t;
        }
        wsum[lane] = w;
    }
    __syncthreads();
    int excl = v - s + (wid > 0 ? wsum[wid - 1] : 0);
    int offset = excl;
    for (int i = start; i < end; i++) {
        int d = g_DEGI[i];
        g_ROWPTR[i] = offset;
        g_CUR[i]    = offset;
        offset += d;
    }
    if (tid == T - 1) g_ROWPTR[M] = offset;
}
__global__ void fill_kernel(const void* __restrict__ ei, int E) {
    int e = blockIdx.x * blockDim.x + threadIdx.x;
    if (e >= E) return;
    int is64 = g_is64;
    int s = edge_at(ei, is64, e);
    int d = edge_at(ei, is64, (long long)E + e);
    int pos = atomicAdd(&g_CUR[d], 1);
    g_SRC[pos] = s;
    g_NRM[pos] = g_DINV[s] * g_DINV[d];
}

// ---------------------------------------------------------------------------
__global__ void w1r_kernel(const float* __restrict__ W1) {
    int idx = blockIdx.x * blockDim.x + threadIdx.x;
    if (idx < CIN * CH) g_W1R[idx] = to_tf32(W1[idx]);
}

// ---------------------------------------------------------------------------
// GEMM1: g_H = X @ W1 via mma.sync.m16n8k8 tf32 (unchanged from R5/R6).
// ---------------------------------------------------------------------------
__global__ __launch_bounds__(256, 2) void gemm1_mma_kernel(
    const float* __restrict__ X, int M)
{
    extern __shared__ float sm[];
    uint32_t smb = smem_u32(sm);

    int tid  = threadIdx.x;
    int wid  = tid >> 5;
    int lane = tid & 31;
    int gid  = lane >> 2;
    int tig  = lane & 3;
    int wm   = wid >> 1;
    int wn   = wid & 1;

    int m0 = blockIdx.x * CTA_M;
    int n0 = blockIdx.y * CTA_N;

    float acc[2][8][4];
    #pragma unroll
    for (int i = 0; i < 2; i++)
        #pragma unroll
        for (int j = 0; j < 8; j++)
            #pragma unroll
            for (int k = 0; k < 4; k++) acc[i][j][k] = 0.0f;

    auto issue = [&](int s, int buf) {
        uint32_t baseA = smb + buf * SM_STAGE;
        uint32_t baseB = baseA + SM_A_BYTES;
        #pragma unroll
        for (int it = 0; it < 4; it++) {
            int id  = it * 256 + tid;
            int ar = id >> 3, akq = id & 7;
            int grow = m0 + ar; if (grow > M - 1) grow = M - 1;
            cp_async16(baseA + (uint32_t)(ar * APAD + akq * 4) * 4,
                       X + (size_t)grow * CIN + s * CTA_K + akq * 4);
            int bk = id >> 5, bnc = id & 31;
            cp_async16(baseB + (uint32_t)(bk * BPAD + bnc * 4) * 4,
                       g_W1R + (size_t)(s * CTA_K + bk) * CH + n0 + bnc * 4);
        }
    };

    issue(0, 0);
    CP_COMMIT();

    for (int s = 0; s < NSTG; s++) {
        int buf = s & 1;
        if (s + 1 < NSTG) {
            issue(s + 1, buf ^ 1);
            CP_COMMIT();
            CP_WAIT(1);
        } else {
            CP_WAIT(0);
        }
        __syncthreads();

        const float* sA = sm + buf * (SM_STAGE / 4);
        const float* sB = sA + (SM_A_BYTES / 4);

        #pragma unroll
        for (int ks = 0; ks < 4; ks++) {
            float a[2][4];
            #pragma unroll
            for (int mt = 0; mt < 2; mt++) {
                int r = wm * 32 + mt * 16 + gid;
                int c = ks * 8 + tig;
                a[mt][0] = to_tf32(sA[r * APAD + c]);
                a[mt][1] = to_tf32(sA[(r + 8) * APAD + c]);
                a[mt][2] = to_tf32(sA[r * APAD + c + 4]);
                a[mt][3] = to_tf32(sA[(r + 8) * APAD + c + 4]);
            }
            float b[8][2];
            #pragma unroll
            for (int nt = 0; nt < 8; nt++) {
                int kk = ks * 8 + tig;
                int cc = wn * 64 + nt * 8 + gid;
                b[nt][0] = sB[kk * BPAD + cc];
                b[nt][1] = sB[(kk + 4) * BPAD + cc];
            }
            #pragma unroll
            for (int mt = 0; mt < 2; mt++)
                #pragma unroll
                for (int nt = 0; nt < 8; nt++)
                    mma_tf32(acc[mt][nt], a[mt], b[nt]);
        }
        __syncthreads();
    }

    #pragma unroll
    for (int mt = 0; mt < 2; mt++) {
        int r0 = m0 + wm * 32 + mt * 16 + gid;
        #pragma unroll
        for (int nt = 0; nt < 8; nt++) {
            int c = n0 + wn * 64 + nt * 8 + 2 * tig;
            if (r0 < M)
                *(float2*)(g_H + (size_t)r0 * CH + c) =
                    make_float2(acc[mt][nt][0], acc[mt][nt][1]);
            if (r0 + 8 < M)
                *(float2*)(g_H + (size_t)(r0 + 8) * CH + c) =
                    make_float2(acc[mt][nt][2], acc[mt][nt][3]);
        }
    }
}

// ---------------------------------------------------------------------------
// threefry2x32, key = (0, 42), partitionable mode: bits = o0 ^ o1
// ---------------------------------------------------------------------------
__device__ __forceinline__ void threefry2x32(unsigned c0, unsigned c1,
                                             unsigned& o0, unsigned& o1) {
    const unsigned ks0 = 0u, ks1 = 42u;
    const unsigned ks2 = 0x1BD11BDAu ^ ks0 ^ ks1;
    unsigned x0 = c0 + ks0;
    unsigned x1 = c1 + ks1;
#define TF_ROUND(r) { x0 += x1; x1 = (x1 << (r)) | (x1 >> (32 - (r))); x1 ^= x0; }
    TF_ROUND(13) TF_ROUND(15) TF_ROUND(26) TF_ROUND(6)
    x0 += ks1; x1 += ks2 + 1u;
    TF_ROUND(17) TF_ROUND(29) TF_ROUND(16) TF_ROUND(24)
    x0 += ks2; x1 += ks0 + 2u;
    TF_ROUND(13) TF_ROUND(15) TF_ROUND(26) TF_ROUND(6)
    x0 += ks0; x1 += ks1 + 3u;
    TF_ROUND(17) TF_ROUND(29) TF_ROUND(16) TF_ROUND(24)
    x0 += ks1; x1 += ks2 + 4u;
    TF_ROUND(13) TF_ROUND(15) TF_ROUND(26) TF_ROUND(6)
    x0 += ks2; x1 += ks0 + 5u;
#undef TF_ROUND
    o0 = x0; o1 = x1;
}

__device__ __forceinline__ float dropout_elu(float acc, float bias, unsigned idx) {
    unsigned o0, o1;
    threefry2x32(0u, idx, o0, o1);
    unsigned bits = o0 ^ o1;
    float u = __uint_as_float((bits >> 9) | 0x3F800000u) - 1.0f;
    float val = acc + bias;
    val = val > 0.0f ? val : expm1f(val);
    return (u < 0.75f) ? val * (1.0f / 0.75f) : 0.0f;
}

// ---------------------------------------------------------------------------
// Layer-1 aggregate + epilogue + fused GEMM2.
// 4 nodes per 256-thread block; 64 threads per node; float4 per thread.
// Edge loop unrolled x4, direct warp-uniform loads of src/nrm (no staging).
// ---------------------------------------------------------------------------
__global__ __launch_bounds__(256) void gather1_kernel(
    const float* __restrict__ b1, const float* __restrict__ W2, int M)
{
    int grp = threadIdx.x >> 6;              // 0..3 node group
    int t   = threadIdx.x & 63;              // thread in group
    int v   = blockIdx.x * 4 + grp;
    bool active = (v < M);
    int vv = active ? v : 0;

    const float4* __restrict__ H4 = (const float4*)g_H;

    float dv = g_DINV[vv];
    float4 h = H4[(size_t)vv * 64 + t];
    float s2 = dv * dv;
    float4 acc = make_float4(s2 * h.x, s2 * h.y, s2 * h.z, s2 * h.w);

    int beg = active ? g_ROWPTR[vv]     : 0;
    int end = active ? g_ROWPTR[vv + 1] : 0;

    int j = beg;
    for (; j + 4 <= end; j += 4) {
        int   s0 = g_SRC[j],     s1 = g_SRC[j + 1];
        int   s2i = g_SRC[j + 2], s3 = g_SRC[j + 3];
        float n0 = g_NRM[j],     n1 = g_NRM[j + 1];
        float n2 = g_NRM[j + 2], n3 = g_NRM[j + 3];
        float4 r0 = H4[(size_t)s0 * 64 + t];
        float4 r1 = H4[(size_t)s1 * 64 + t];
        float4 r2 = H4[(size_t)s2i * 64 + t];
        float4 r3 = H4[(size_t)s3 * 64 + t];
        acc.x += n0 * r0.x + n1 * r1.x + n2 * r2.x + n3 * r3.x;
        acc.y += n0 * r0.y + n1 * r1.y + n2 * r2.y + n3 * r3.y;
        acc.z += n0 * r0.z + n1 * r1.z + n2 * r2.z + n3 * r3.z;
        acc.w += n0 * r0.w + n1 * r1.w + n2 * r2.w + n3 * r3.w;
    }
    for (; j < end; j++) {
        int   s0 = g_SRC[j];
        float n0 = g_NRM[j];
        float4 r0 = H4[(size_t)s0 * 64 + t];
        acc.x += n0 * r0.x;
        acc.y += n0 * r0.y;
        acc.z += n0 * r0.z;
        acc.w += n0 * r0.w;
    }

    // epilogue: bias + ELU + dropout, 4 channels per thread
    float4 bb = ((const float4*)b1)[t];
    unsigned base = (unsigned)vv * CH + (unsigned)t * 4;
    float a0 = dropout_elu(acc.x, bb.x, base + 0);
    float a1 = dropout_elu(acc.y, bb.y, base + 1);
    float a2 = dropout_elu(acc.z, bb.z, base + 2);
    float a3 = dropout_elu(acc.w, bb.w, base + 3);

    // fused GEMM2: P[v] = sum_c act[c] * W2[c]
    float4 w = ((const float4*)W2)[t];
    float dot = a0 * w.x + a1 * w.y + a2 * w.z + a3 * w.w;
    #pragma unroll
    for (int o = 16; o > 0; o >>= 1)
        dot += __shfl_xor_sync(0xffffffffu, dot, o);

    __shared__ float red[8];                 // 4 groups x 2 warps
    int lane = t & 31, hw = t >> 5;
    if (lane == 0) red[grp * 2 + hw] = dot;
    __syncthreads();
    if (t == 0 && active) g_P[v] = red[grp * 2] + red[grp * 2 + 1];
}

// ---------------------------------------------------------------------------
// Layer-2 aggregate (CSR gather, scalar). One warp per node.
// ---------------------------------------------------------------------------
__global__ void gather2_kernel(const float* __restrict__ b2,
                               float* __restrict__ out, int M) {
    int gt   = blockIdx.x * blockDim.x + threadIdx.x;
    int warp = gt >> 5;
    int lane = gt & 31;
    if (warp >= M) return;
    int beg = g_ROWPTR[warp];
    int end = g_ROWPTR[warp + 1];
    float s = 0.0f;
    for (int e = beg + lane; e < end; e += 32)
        s += g_NRM[e] * g_P[g_SRC[e]];
    #pragma unroll
    for (int o = 16; o > 0; o >>= 1) s += __shfl_xor_sync(0xffffffffu, s, o);
    if (lane == 0) {
        float dv = g_DINV[warp];
        out[warp] = dv * dv * g_P[warp] + b2[0] + s;
    }
}

// ---------------------------------------------------------------------------
extern "C" void kernel_launch(void* const* d_in, const int* in_sizes, int n_in,
                              void* d_out, int out_size) {
    const float* x  = (const float*)d_in[0];
    const void*  ei = d_in[1];
    const float* W1 = (const float*)d_in[2];
    const float* b1 = (const float*)d_in[3];
    const float* W2 = (const float*)d_in[4];
    const float* b2 = (const float*)d_in[5];
    float* out = (float*)d_out;

    int M = in_sizes[0] / CIN;     // 50000
    int E = in_sizes[1] / 2;       // 800000

    static int cfg = 0;
    if (!cfg) {
        cudaFuncSetAttribute(gemm1_mma_kernel,
                             cudaFuncAttributeMaxDynamicSharedMemorySize, SM_TOTAL);
        cfg = 1;
    }

    detect_kernel<<<1, 32>>>((const unsigned*)ei, E);

    // CSR build
    deg_zero_kernel<<<(M + 255) / 256, 256>>>(M);
    deg_acc_kernel <<<(E + 255) / 256, 256>>>(ei, E);
    dinv_kernel    <<<(M + 255) / 256, 256>>>(M);
    scan_kernel    <<<1, 1024>>>(M);
    fill_kernel    <<<(E + 255) / 256, 256>>>(ei, E);

    // Layer 1 (+ fused GEMM2)
    w1r_kernel<<<(CIN * CH + 255) / 256, 256>>>(W1);
    dim3 g1((M + CTA_M - 1) / CTA_M, CH / CTA_N);  // (391, 2)
    gemm1_mma_kernel<<<g1, 256, SM_TOTAL>>>(x, M);
    gather1_kernel<<<(M + 3) / 4, 256>>>(b1, W2, M);

    // Layer 2
    gather2_kernel<<<(M * 32 + 255) / 256, 256>>>(b2, out, M);
}

// round 8
// speedup vs baseline: 3.2158x; 1.0139x over previous
#include <cuda_runtime.h>
#include <cstdint>

// ---------------------------------------------------------------------------
// GCN 2-layer forward on GB300 — round 8: CSR build overlapped with GEMM1
// via stream fork-join inside graph capture. Kernels identical to R7.
//   h  = x @ W1                 (mma.sync tf32, 50000x512 @ 512x256)
//   a1 = Dinv (A+I) Dinv h ; +b1 ; ELU ; dropout(p=0.25, jax threefry)
//   p  = a1 @ W2                (fused: group dot-product in gather1)
//   out= Dinv (A+I) Dinv p + b2
// ---------------------------------------------------------------------------

#define NMAX 50048
#define EMAX 1000000
#define CIN  512
#define CH   256

// GEMM1 tiling
#define CTA_M 128
#define CTA_N 128
#define CTA_K 32
#define NSTG  (CIN / CTA_K)          // 16
#define APAD  36
#define BPAD  136
#define SM_A_BYTES (CTA_M * APAD * 4)
#define SM_B_BYTES (CTA_K * BPAD * 4)
#define SM_STAGE   (SM_A_BYTES + SM_B_BYTES)
#define SM_TOTAL   (2 * SM_STAGE)

__device__ int   g_DEGI[NMAX];
__device__ float g_DINV[NMAX];
__device__ int   g_ROWPTR[NMAX + 1];
__device__ int   g_CUR[NMAX];
__device__ int   g_SRC[EMAX];
__device__ float g_NRM[EMAX];
__device__ float g_H  [(size_t)NMAX * CH];
__device__ float g_P  [NMAX];
__device__ float g_W1R[(size_t)CIN * CH];
__device__ int   g_is64;

__device__ __forceinline__ float to_tf32(float x) {
    float r;
    asm("cvt.rna.tf32.f32 %0, %1;" : "=f"(r) : "f"(x));
    return r;
}
__device__ __forceinline__ uint32_t smem_u32(const void* p) {
    uint32_t a;
    asm("{ .reg .u64 t; cvta.to.shared.u64 t, %1; cvt.u32.u64 %0, t; }"
        : "=r"(a) : "l"(p));
    return a;
}
__device__ __forceinline__ void cp_async16(uint32_t dst, const void* src) {
    asm volatile("cp.async.ca.shared.global [%0], [%1], 16;"
                 :: "r"(dst), "l"(src));
}
#define CP_COMMIT() asm volatile("cp.async.commit_group;" ::: "memory")
#define CP_WAIT(n)  asm volatile("cp.async.wait_group %0;" :: "n"(n) : "memory")

__device__ __forceinline__ void mma_tf32(float* c, const float* a, const float* b) {
    asm volatile(
        "mma.sync.aligned.m16n8k8.row.col.f32.tf32.tf32.f32 "
        "{%0,%1,%2,%3}, {%4,%5,%6,%7}, {%8,%9}, {%0,%1,%2,%3};"
        : "+f"(c[0]), "+f"(c[1]), "+f"(c[2]), "+f"(c[3])
        : "r"(__float_as_uint(a[0])), "r"(__float_as_uint(a[1])),
          "r"(__float_as_uint(a[2])), "r"(__float_as_uint(a[3])),
          "r"(__float_as_uint(b[0])), "r"(__float_as_uint(b[1])));
}

// ---------------------------------------------------------------------------
__global__ void detect_kernel(const unsigned* __restrict__ words, int E) {
    if (threadIdx.x == 0 && blockIdx.x == 0) {
        int n = E < 256 ? E : 256;
        unsigned acc = 0u;
        for (int i = 0; i < n; i++) acc |= words[2 * i + 1];
        g_is64 = (acc == 0u) ? 1 : 0;
    }
}
__device__ __forceinline__ int edge_at(const void* ei, int is64, long long idx) {
    if (is64) return (int)((const long long*)ei)[idx];
    return ((const int*)ei)[idx];
}

// ---------------------------------------------------------------------------
__global__ void deg_zero_kernel(int M) {
    int v = blockIdx.x * blockDim.x + threadIdx.x;
    if (v < M) g_DEGI[v] = 0;
}
__global__ void deg_acc_kernel(const void* __restrict__ ei, int E) {
    int e = blockIdx.x * blockDim.x + threadIdx.x;
    if (e >= E) return;
    int d = edge_at(ei, g_is64, (long long)E + e);
    atomicAdd(&g_DEGI[d], 1);
}
__global__ void dinv_kernel(int M) {
    int v = blockIdx.x * blockDim.x + threadIdx.x;
    if (v < M) g_DINV[v] = rsqrtf((float)(g_DEGI[v] + 1));
}
__global__ __launch_bounds__(1024) void scan_kernel(int M) {
    const int T = 1024;
    int tid = threadIdx.x;
    int chunk = (M + T - 1) / T;
    int start = tid * chunk;
    int end   = start + chunk; if (end > M) end = M; if (start > M) start = M;
    int s = 0;
    for (int i = start; i < end; i++) s += g_DEGI[i];
    int lane = tid & 31, wid = tid >> 5;
    int v = s;
    #pragma unroll
    for (int o = 1; o < 32; o <<= 1) {
        int t = __shfl_up_sync(0xffffffffu, v, o);
        if (lane >= o) v += t;
    }
    __shared__ int wsum[32];
    if (lane == 31) wsum[wid] = v;
    __syncthreads();
    if (wid == 0) {
        int w = wsum[lane];
        #pragma unroll
        for (int o = 1; o < 32; o <<= 1) {
            int t = __shfl_up_sync(0xffffffffu, w, o);
            if (lane >= o) w += t;
        }
        wsum[lane] = w;
    }
    __syncthreads();
    int excl = v - s + (wid > 0 ? wsum[wid - 1] : 0);
    int offset = excl;
    for (int i = start; i < end; i++) {
        int d = g_DEGI[i];
        g_ROWPTR[i] = offset;
        g_CUR[i]    = offset;
        offset += d;
    }
    if (tid == T - 1) g_ROWPTR[M] = offset;
}
__global__ void fill_kernel(const void* __restrict__ ei, int E) {
    int e = blockIdx.x * blockDim.x + threadIdx.x;
    if (e >= E) return;
    int is64 = g_is64;
    int s = edge_at(ei, is64, e);
    int d = edge_at(ei, is64, (long long)E + e);
    int pos = atomicAdd(&g_CUR[d], 1);
    g_SRC[pos] = s;
    g_NRM[pos] = g_DINV[s] * g_DINV[d];
}

// ---------------------------------------------------------------------------
__global__ void w1r_kernel(const float* __restrict__ W1) {
    int idx = blockIdx.x * blockDim.x + threadIdx.x;
    if (idx < CIN * CH) g_W1R[idx] = to_tf32(W1[idx]);
}

// ---------------------------------------------------------------------------
// GEMM1: g_H = X @ W1 via mma.sync.m16n8k8 tf32 (unchanged from R5-R7).
// ---------------------------------------------------------------------------
__global__ __launch_bounds__(256, 2) void gemm1_mma_kernel(
    const float* __restrict__ X, int M)
{
    extern __shared__ float sm[];
    uint32_t smb = smem_u32(sm);

    int tid  = threadIdx.x;
    int wid  = tid >> 5;
    int lane = tid & 31;
    int gid  = lane >> 2;
    int tig  = lane & 3;
    int wm   = wid >> 1;
    int wn   = wid & 1;

    int m0 = blockIdx.x * CTA_M;
    int n0 = blockIdx.y * CTA_N;

    float acc[2][8][4];
    #pragma unroll
    for (int i = 0; i < 2; i++)
        #pragma unroll
        for (int j = 0; j < 8; j++)
            #pragma unroll
            for (int k = 0; k < 4; k++) acc[i][j][k] = 0.0f;

    auto issue = [&](int s, int buf) {
        uint32_t baseA = smb + buf * SM_STAGE;
        uint32_t baseB = baseA + SM_A_BYTES;
        #pragma unroll
        for (int it = 0; it < 4; it++) {
            int id  = it * 256 + tid;
            int ar = id >> 3, akq = id & 7;
            int grow = m0 + ar; if (grow > M - 1) grow = M - 1;
            cp_async16(baseA + (uint32_t)(ar * APAD + akq * 4) * 4,
                       X + (size_t)grow * CIN + s * CTA_K + akq * 4);
            int bk = id >> 5, bnc = id & 31;
            cp_async16(baseB + (uint32_t)(bk * BPAD + bnc * 4) * 4,
                       g_W1R + (size_t)(s * CTA_K + bk) * CH + n0 + bnc * 4);
        }
    };

    issue(0, 0);
    CP_COMMIT();

    for (int s = 0; s < NSTG; s++) {
        int buf = s & 1;
        if (s + 1 < NSTG) {
            issue(s + 1, buf ^ 1);
            CP_COMMIT();
            CP_WAIT(1);
        } else {
            CP_WAIT(0);
        }
        __syncthreads();

        const float* sA = sm + buf * (SM_STAGE / 4);
        const float* sB = sA + (SM_A_BYTES / 4);

        #pragma unroll
        for (int ks = 0; ks < 4; ks++) {
            float a[2][4];
            #pragma unroll
            for (int mt = 0; mt < 2; mt++) {
                int r = wm * 32 + mt * 16 + gid;
                int c = ks * 8 + tig;
                a[mt][0] = to_tf32(sA[r * APAD + c]);
                a[mt][1] = to_tf32(sA[(r + 8) * APAD + c]);
                a[mt][2] = to_tf32(sA[r * APAD + c + 4]);
                a[mt][3] = to_tf32(sA[(r + 8) * APAD + c + 4]);
            }
            float b[8][2];
            #pragma unroll
            for (int nt = 0; nt < 8; nt++) {
                int kk = ks * 8 + tig;
                int cc = wn * 64 + nt * 8 + gid;
                b[nt][0] = sB[kk * BPAD + cc];
                b[nt][1] = sB[(kk + 4) * BPAD + cc];
            }
            #pragma unroll
            for (int mt = 0; mt < 2; mt++)
                #pragma unroll
                for (int nt = 0; nt < 8; nt++)
                    mma_tf32(acc[mt][nt], a[mt], b[nt]);
        }
        __syncthreads();
    }

    #pragma unroll
    for (int mt = 0; mt < 2; mt++) {
        int r0 = m0 + wm * 32 + mt * 16 + gid;
        #pragma unroll
        for (int nt = 0; nt < 8; nt++) {
            int c = n0 + wn * 64 + nt * 8 + 2 * tig;
            if (r0 < M)
                *(float2*)(g_H + (size_t)r0 * CH + c) =
                    make_float2(acc[mt][nt][0], acc[mt][nt][1]);
            if (r0 + 8 < M)
                *(float2*)(g_H + (size_t)(r0 + 8) * CH + c) =
                    make_float2(acc[mt][nt][2], acc[mt][nt][3]);
        }
    }
}

// ---------------------------------------------------------------------------
// threefry2x32, key = (0, 42), partitionable mode: bits = o0 ^ o1
// ---------------------------------------------------------------------------
__device__ __forceinline__ void threefry2x32(unsigned c0, unsigned c1,
                                             unsigned& o0, unsigned& o1) {
    const unsigned ks0 = 0u, ks1 = 42u;
    const unsigned ks2 = 0x1BD11BDAu ^ ks0 ^ ks1;
    unsigned x0 = c0 + ks0;
    unsigned x1 = c1 + ks1;
#define TF_ROUND(r) { x0 += x1; x1 = (x1 << (r)) | (x1 >> (32 - (r))); x1 ^= x0; }
    TF_ROUND(13) TF_ROUND(15) TF_ROUND(26) TF_ROUND(6)
    x0 += ks1; x1 += ks2 + 1u;
    TF_ROUND(17) TF_ROUND(29) TF_ROUND(16) TF_ROUND(24)
    x0 += ks2; x1 += ks0 + 2u;
    TF_ROUND(13) TF_ROUND(15) TF_ROUND(26) TF_ROUND(6)
    x0 += ks0; x1 += ks1 + 3u;
    TF_ROUND(17) TF_ROUND(29) TF_ROUND(16) TF_ROUND(24)
    x0 += ks1; x1 += ks2 + 4u;
    TF_ROUND(13) TF_ROUND(15) TF_ROUND(26) TF_ROUND(6)
    x0 += ks2; x1 += ks0 + 5u;
#undef TF_ROUND
    o0 = x0; o1 = x1;
}

__device__ __forceinline__ float dropout_elu(float acc, float bias, unsigned idx) {
    unsigned o0, o1;
    threefry2x32(0u, idx, o0, o1);
    unsigned bits = o0 ^ o1;
    float u = __uint_as_float((bits >> 9) | 0x3F800000u) - 1.0f;
    float val = acc + bias;
    val = val > 0.0f ? val : expm1f(val);
    return (u < 0.75f) ? val * (1.0f / 0.75f) : 0.0f;
}

// ---------------------------------------------------------------------------
// Layer-1 aggregate + epilogue + fused GEMM2 (unchanged from R7).
// ---------------------------------------------------------------------------
__global__ __launch_bounds__(256) void gather1_kernel(
    const float* __restrict__ b1, const float* __restrict__ W2, int M)
{
    int grp = threadIdx.x >> 6;
    int t   = threadIdx.x & 63;
    int v   = blockIdx.x * 4 + grp;
    bool active = (v < M);
    int vv = active ? v : 0;

    const float4* __restrict__ H4 = (const float4*)g_H;

    float dv = g_DINV[vv];
    float4 h = H4[(size_t)vv * 64 + t];
    float s2 = dv * dv;
    float4 acc = make_float4(s2 * h.x, s2 * h.y, s2 * h.z, s2 * h.w);

    int beg = active ? g_ROWPTR[vv]     : 0;
    int end = active ? g_ROWPTR[vv + 1] : 0;

    int j = beg;
    for (; j + 4 <= end; j += 4) {
        int   s0 = g_SRC[j],     s1 = g_SRC[j + 1];
        int   s2i = g_SRC[j + 2], s3 = g_SRC[j + 3];
        float n0 = g_NRM[j],     n1 = g_NRM[j + 1];
        float n2 = g_NRM[j + 2], n3 = g_NRM[j + 3];
        float4 r0 = H4[(size_t)s0 * 64 + t];
        float4 r1 = H4[(size_t)s1 * 64 + t];
        float4 r2 = H4[(size_t)s2i * 64 + t];
        float4 r3 = H4[(size_t)s3 * 64 + t];
        acc.x += n0 * r0.x + n1 * r1.x + n2 * r2.x + n3 * r3.x;
        acc.y += n0 * r0.y + n1 * r1.y + n2 * r2.y + n3 * r3.y;
        acc.z += n0 * r0.z + n1 * r1.z + n2 * r2.z + n3 * r3.z;
        acc.w += n0 * r0.w + n1 * r1.w + n2 * r2.w + n3 * r3.w;
    }
    for (; j < end; j++) {
        int   s0 = g_SRC[j];
        float n0 = g_NRM[j];
        float4 r0 = H4[(size_t)s0 * 64 + t];
        acc.x += n0 * r0.x;
        acc.y += n0 * r0.y;
        acc.z += n0 * r0.z;
        acc.w += n0 * r0.w;
    }

    float4 bb = ((const float4*)b1)[t];
    unsigned base = (unsigned)vv * CH + (unsigned)t * 4;
    float a0 = dropout_elu(acc.x, bb.x, base + 0);
    float a1 = dropout_elu(acc.y, bb.y, base + 1);
    float a2 = dropout_elu(acc.z, bb.z, base + 2);
    float a3 = dropout_elu(acc.w, bb.w, base + 3);

    float4 w = ((const float4*)W2)[t];
    float dot = a0 * w.x + a1 * w.y + a2 * w.z + a3 * w.w;
    #pragma unroll
    for (int o = 16; o > 0; o >>= 1)
        dot += __shfl_xor_sync(0xffffffffu, dot, o);

    __shared__ float red[8];
    int lane = t & 31, hw = t >> 5;
    if (lane == 0) red[grp * 2 + hw] = dot;
    __syncthreads();
    if (t == 0 && active) g_P[v] = red[grp * 2] + red[grp * 2 + 1];
}

// ---------------------------------------------------------------------------
// Layer-2 aggregate (CSR gather, scalar). One warp per node.
// ---------------------------------------------------------------------------
__global__ void gather2_kernel(const float* __restrict__ b2,
                               float* __restrict__ out, int M) {
    int gt   = blockIdx.x * blockDim.x + threadIdx.x;
    int warp = gt >> 5;
    int lane = gt & 31;
    if (warp >= M) return;
    int beg = g_ROWPTR[warp];
    int end = g_ROWPTR[warp + 1];
    float s = 0.0f;
    for (int e = beg + lane; e < end; e += 32)
        s += g_NRM[e] * g_P[g_SRC[e]];
    #pragma unroll
    for (int o = 16; o > 0; o >>= 1) s += __shfl_xor_sync(0xffffffffu, s, o);
    if (lane == 0) {
        float dv = g_DINV[warp];
        out[warp] = dv * dv * g_P[warp] + b2[0] + s;
    }
}

// ---------------------------------------------------------------------------
extern "C" void kernel_launch(void* const* d_in, const int* in_sizes, int n_in,
                              void* d_out, int out_size) {
    const float* x  = (const float*)d_in[0];
    const void*  ei = d_in[1];
    const float* W1 = (const float*)d_in[2];
    const float* b1 = (const float*)d_in[3];
    const float* W2 = (const float*)d_in[4];
    const float* b2 = (const float*)d_in[5];
    float* out = (float*)d_out;

    int M = in_sizes[0] / CIN;     // 50000
    int E = in_sizes[1] / 2;       // 800000

    static cudaStream_t s2 = nullptr;
    static cudaEvent_t evFork = nullptr, evJoin = nullptr;
    if (!s2) {
        cudaFuncSetAttribute(gemm1_mma_kernel,
                             cudaFuncAttributeMaxDynamicSharedMemorySize, SM_TOTAL);
        cudaStreamCreateWithFlags(&s2, cudaStreamNonBlocking);
        cudaEventCreateWithFlags(&evFork, cudaEventDisableTiming);
        cudaEventCreateWithFlags(&evJoin, cudaEventDisableTiming);
    }

    // ---- fork: CSR build on s2, GEMM1 on stream 0 (capture origin) ----
    cudaEventRecord(evFork, 0);
    cudaStreamWaitEvent(s2, evFork, 0);

    // branch A (s2): edge-index detect + CSR build
    detect_kernel  <<<1, 32, 0, s2>>>((const unsigned*)ei, E);
    deg_zero_kernel<<<(M + 255) / 256, 256, 0, s2>>>(M);
    deg_acc_kernel <<<(E + 255) / 256, 256, 0, s2>>>(ei, E);
    dinv_kernel    <<<(M + 255) / 256, 256, 0, s2>>>(M);
    scan_kernel    <<<1, 1024, 0, s2>>>(M);
    fill_kernel    <<<(E + 255) / 256, 256, 0, s2>>>(ei, E);

    // branch B (stream 0): W1 round + GEMM1
    w1r_kernel<<<(CIN * CH + 255) / 256, 256>>>(W1);
    dim3 g1((M + CTA_M - 1) / CTA_M, CH / CTA_N);  // (391, 2)
    gemm1_mma_kernel<<<g1, 256, SM_TOTAL>>>(x, M);

    // ---- join on stream 0 ----
    cudaEventRecord(evJoin, s2);
    cudaStreamWaitEvent(0, evJoin, 0);

    // Layer 1 aggregate (+ fused GEMM2), then layer 2
    gather1_kernel<<<(M + 3) / 4, 256>>>(b1, W2, M);
    gather2_kernel<<<(M * 32 + 255) / 256, 256>>>(b2, out, M);
}